// round 17
// baseline (speedup 1.0000x reference)
#include <cuda_runtime.h>
#include <cuda_fp16.h>
#include <cstdint>

// Problem shape (fixed): B=4, T=2048, C=2048, H=16, d=128
#define BATCH 4
#define TQ    2048
#define CH    2048
#define NHEAD 16
#define HDIM  128
#define C3    6144
#define KC    64            // K halves per pipeline stage (GEMM)
#define NSTAGE 3
// GEMM stage: A 256x64 (32KB) + B 128x64 (16KB)
#define GSTAGE 49152
#define SMEM_BYTES (NSTAGE * GSTAGE)   // 144 KB

// Flash smem layout (dynamic): Q | K(2 stages) | Vt(2 stages) | P
#define FSM_Q 0
#define FSM_K 32768
#define FSM_V (3 * 32768)
#define FSM_P (5 * 32768)
#define FSM_TOTAL (5 * 32768 + 128 * 272)   // 198656

// ---- scratch (device globals; no allocation allowed) ----
__device__ __half g_xh  [(size_t)BATCH * TQ * CH];
__device__ __half g_wah [(size_t)C3 * CH];
__device__ __half g_wph [(size_t)CH * CH];
__device__ __half g_qkvh[(size_t)BATCH * TQ * C3];
__device__ __half g_outh[(size_t)BATCH * TQ * CH];
__device__ __half g_vth [(size_t)BATCH * NHEAD * HDIM * TQ];

static __device__ __forceinline__ uint32_t su32(const void* p) {
    uint32_t a;
    asm("{ .reg .u64 t; cvta.to.shared.u64 t, %1; cvt.u32.u64 %0, t; }" : "=r"(a) : "l"(p));
    return a;
}
#define CPA(d, s) asm volatile("cp.async.cg.shared.global [%0], [%1], 16;" \
    :: "r"(d), "l"(__cvta_generic_to_global(s)) : "memory")
#define CPCOMMIT() asm volatile("cp.async.commit_group;" ::: "memory")
#define CPWAIT1()  asm volatile("cp.async.wait_group 1;" ::: "memory")
#define CPWAIT0()  asm volatile("cp.async.wait_group 0;" ::: "memory")

#define LDSM4(r0, r1, r2, r3, ad) \
    asm volatile("ldmatrix.sync.aligned.m8n8.x4.shared.b16 {%0,%1,%2,%3}, [%4];" \
        : "=r"(r0), "=r"(r1), "=r"(r2), "=r"(r3) : "r"(ad))

#define MMA16816(acc, af, bf) \
    asm volatile("mma.sync.aligned.m16n8k16.row.col.f32.f16.f16.f32 " \
        "{%0,%1,%2,%3}, {%4,%5,%6,%7}, {%8,%9}, {%0,%1,%2,%3};" \
        : "+f"((acc)[0]), "+f"((acc)[1]), "+f"((acc)[2]), "+f"((acc)[3]) \
        : "r"((af)[0]), "r"((af)[1]), "r"((af)[2]), "r"((af)[3]), \
          "r"((bf)[0]), "r"((bf)[1]))

// ---------------------------------------------------------------------------
// f16 tensor-core NT GEMM:  C[M,N] = A[M,K] * B[N,K]^T   (fp32 accumulate)
// CTA tile 256x128, warp tile 64x64 (4 m-warps x 2 n-warps, 256 threads),
// KC=64 halves/stage, 3-stage cp.async pipeline, 1 sync per chunk.
// ---------------------------------------------------------------------------
template<bool OUTF16>
__global__ void __launch_bounds__(256, 1)
gemm_h(const __half* __restrict__ A, int lda,
       const __half* __restrict__ B, int ldb,
       void* __restrict__ Cv, int ldc, int K)
{
    extern __shared__ char smem[];
    const uint32_t smb = su32(smem);

    const int tid = threadIdx.x, wid = tid >> 5, lane = tid & 31;
    const __half* Ab = A + (size_t)blockIdx.y * 256 * lda;
    const __half* Bb = B + (size_t)blockIdx.x * 128 * ldb;
    const int nch = K / KC;

    const int fr = tid >> 3;          // row 0..31 (+32 per iter)
    const int fc = tid & 7;           // 16B chunk 0..7
    const int rA   = (lane & 7) + ((lane >> 3) & 1) * 8;
    const int ksel = lane >> 4;
    const int wm   = (wid & 3) * 64;  // 4 m-warps
    const int wn   = (wid >> 2) * 64; // 2 n-warps

    float acc[4][8][4];
#pragma unroll
    for (int i = 0; i < 4; i++)
#pragma unroll
        for (int j = 0; j < 8; j++)
#pragma unroll
            for (int r = 0; r < 4; r++) acc[i][j][r] = 0.f;

    auto issue = [&](int ch) {
        const uint32_t sa = smb + (ch % NSTAGE) * GSTAGE;
        const uint32_t sb = sa + 32768;
        const __half* ga = Ab + ch * KC;
        const __half* gb = Bb + ch * KC;
#pragma unroll
        for (int it = 0; it < 8; it++) {          // A: 256 rows
            const int r = fr + it * 32;
            const uint32_t sw = (uint32_t)((fc ^ (r & 7)) << 4);
            CPA(sa + r * 128 + sw, ga + (size_t)r * lda + fc * 8);
        }
#pragma unroll
        for (int it = 0; it < 4; it++) {          // B: 128 rows
            const int r = fr + it * 32;
            const uint32_t sw = (uint32_t)((fc ^ (r & 7)) << 4);
            CPA(sb + r * 128 + sw, gb + (size_t)r * ldb + fc * 8);
        }
    };

    issue(0); CPCOMMIT();
    if (nch > 1) { issue(1); CPCOMMIT(); }

    for (int i = 0; i < nch; i++) {
        if (i == nch - 1) CPWAIT0(); else CPWAIT1();
        __syncthreads();               // stage i ready; also guards stage reuse
        if (i + 2 < nch) { issue(i + 2); CPCOMMIT(); }

        const uint32_t sa = smb + (i % NSTAGE) * GSTAGE;
        const uint32_t sb = sa + 32768;
#pragma unroll
        for (int kk = 0; kk < 4; kk++) {
            const uint32_t col = (uint32_t)(((kk * 2 + ksel) ^ (rA & 7)) << 4);
            uint32_t a[4][4];
#pragma unroll
            for (int mt = 0; mt < 4; mt++)
                LDSM4(a[mt][0], a[mt][1], a[mt][2], a[mt][3],
                      sa + (uint32_t)(wm + mt * 16 + rA) * 128 + col);
            uint32_t b[8][2];
#pragma unroll
            for (int pr = 0; pr < 4; pr++) {
                uint32_t r0, r1, r2, r3;
                LDSM4(r0, r1, r2, r3, sb + (uint32_t)(wn + pr * 16 + rA) * 128 + col);
                b[pr * 2][0] = r0; b[pr * 2 + 1][0] = r1;
                b[pr * 2][1] = r2; b[pr * 2 + 1][1] = r3;
            }
#pragma unroll
            for (int mt = 0; mt < 4; mt++)
#pragma unroll
                for (int nt = 0; nt < 8; nt++)
                    MMA16816(acc[mt][nt], a[mt], b[nt]);
        }
    }

    const int g = lane >> 2, t = lane & 3;
    if (OUTF16) {
        __syncthreads();               // all reads of last stage done before staging
        __half* Cb = (__half*)Cv + (size_t)blockIdx.y * 256 * ldc + (size_t)blockIdx.x * 128;
        __half* eb = (__half*)smem;    // [256][136] halves = 69632 B
#pragma unroll
        for (int mt = 0; mt < 4; mt++) {
            const int r0 = wm + mt * 16 + g;
#pragma unroll
            for (int nt = 0; nt < 8; nt++) {
                const int c0 = wn + nt * 8 + 2 * t;
                *(__half2*)&eb[r0 * 136 + c0]       = __floats2half2_rn(acc[mt][nt][0], acc[mt][nt][1]);
                *(__half2*)&eb[(r0 + 8) * 136 + c0] = __floats2half2_rn(acc[mt][nt][2], acc[mt][nt][3]);
            }
        }
        __syncthreads();
        // 256 rows x 16 chunks of 8 halves = 4096 chunks
#pragma unroll
        for (int it = 0; it < 16; it++) {
            const int idx = tid + it * 256;
            const int r = idx >> 4, c = idx & 15;
            uint4 v = *(const uint4*)&eb[r * 136 + c * 8];
            *(uint4*)(Cb + (size_t)r * ldc + c * 8) = v;
        }
    } else {
        float* Cb = (float*)Cv + (size_t)blockIdx.y * 256 * ldc + (size_t)blockIdx.x * 128;
#pragma unroll
        for (int mt = 0; mt < 4; mt++) {
            const int r0 = wm + mt * 16 + g;
#pragma unroll
            for (int nt = 0; nt < 8; nt++) {
                const int c0 = wn + nt * 8 + 2 * t;
                *(float2*)(Cb + (size_t)r0 * ldc + c0)       = make_float2(acc[mt][nt][0], acc[mt][nt][1]);
                *(float2*)(Cb + (size_t)(r0 + 8) * ldc + c0) = make_float2(acc[mt][nt][2], acc[mt][nt][3]);
            }
        }
    }
}

// ---------------------------------------------------------------------------
// Fused flash attention: per CTA one 128-row q-block of one (b,h).
// (validated in round 14; unchanged)
// ---------------------------------------------------------------------------
__global__ void __launch_bounds__(256, 1)
flash_attn()
{
    extern __shared__ char smem[];
    const uint32_t smb = su32(smem);
    __shared__ float sredm[128][4];
    __shared__ float sreds[128][4];

    const int tid = threadIdx.x, wid = tid >> 5, lane = tid & 31;
    const int ib = 15 - (int)blockIdx.x;
    const int z  = (int)blockIdx.y;
    const int zb = z >> 4, zh = z & 15;

    const __half* gQ  = g_qkvh + (size_t)zb * TQ * C3 + zh * HDIM + (size_t)ib * 128 * C3;
    const __half* gK  = g_qkvh + (size_t)zb * TQ * C3 + CH + zh * HDIM;
    const __half* gVt = g_vth + (size_t)z * HDIM * TQ;

    const int fr = tid >> 3, fc = tid & 7;
    const int rA   = (lane & 7) + ((lane >> 3) & 1) * 8;
    const int ksel = lane >> 4;
    const int wm   = (wid & 1) * 64;
    const int wn   = (wid >> 1) * 32;
    const int g = lane >> 2, t = lane & 3;
    const int nw = wid >> 1;
    const float scale = 0.08838834764831844f;

    auto issueKV = [&](int jb, int s) {
        const uint32_t kk = smb + FSM_K + s * 32768;
        const uint32_t vv = smb + FSM_V + s * 32768;
#pragma unroll
        for (int ch = 0; ch < 2; ch++)
#pragma unroll
            for (int it = 0; it < 4; it++) {
                const int r = fr + it * 32;
                const uint32_t sw = (uint32_t)((fc ^ (r & 7)) << 4);
                CPA(kk + ch * 16384 + r * 128 + sw,
                    gK + (size_t)(jb * 128 + r) * C3 + ch * 64 + fc * 8);
                CPA(vv + ch * 16384 + r * 128 + sw,
                    gVt + (size_t)r * TQ + jb * 128 + ch * 64 + fc * 8);
            }
    };

    {
#pragma unroll
        for (int ch = 0; ch < 2; ch++)
#pragma unroll
            for (int it = 0; it < 4; it++) {
                const int r = fr + it * 32;
                const uint32_t sw = (uint32_t)((fc ^ (r & 7)) << 4);
                CPA(smb + FSM_Q + ch * 16384 + r * 128 + sw,
                    gQ + (size_t)r * C3 + ch * 64 + fc * 8);
            }
        issueKV(0, 0);
        CPCOMMIT();
    }

    float acc_o[4][4][4];
#pragma unroll
    for (int i = 0; i < 4; i++)
#pragma unroll
        for (int j = 0; j < 4; j++)
#pragma unroll
            for (int r = 0; r < 4; r++) acc_o[i][j][r] = 0.f;
    float m_i[8], l_i[8];
#pragma unroll
    for (int r = 0; r < 8; r++) { m_i[r] = -1e30f; l_i[r] = 0.f; }

    for (int jb = 0; jb <= ib; jb++) {
        const int s = jb & 1;
        CPWAIT0();
        __syncthreads();
        if (jb < ib) { issueKV(jb + 1, s ^ 1); CPCOMMIT(); }

        float acc_s[4][4][4];
#pragma unroll
        for (int i = 0; i < 4; i++)
#pragma unroll
            for (int j = 0; j < 4; j++)
#pragma unroll
                for (int r = 0; r < 4; r++) acc_s[i][j][r] = 0.f;

        const uint32_t qb = smb + FSM_Q;
        const uint32_t kb = smb + FSM_K + s * 32768;
#pragma unroll
        for (int ch = 0; ch < 2; ch++)
#pragma unroll
            for (int kk = 0; kk < 4; kk++) {
                const uint32_t col = (uint32_t)(((kk * 2 + ksel) ^ (rA & 7)) << 4);
                uint32_t a[4][4];
#pragma unroll
                for (int mt = 0; mt < 4; mt++)
                    LDSM4(a[mt][0], a[mt][1], a[mt][2], a[mt][3],
                          qb + ch * 16384 + (uint32_t)(wm + mt * 16 + rA) * 128 + col);
                uint32_t b[4][2];
#pragma unroll
                for (int pr = 0; pr < 2; pr++) {
                    uint32_t r0, r1, r2, r3;
                    LDSM4(r0, r1, r2, r3,
                          kb + ch * 16384 + (uint32_t)(wn + pr * 16 + rA) * 128 + col);
                    b[pr * 2][0] = r0; b[pr * 2 + 1][0] = r1;
                    b[pr * 2][1] = r2; b[pr * 2 + 1][1] = r3;
                }
#pragma unroll
                for (int mt = 0; mt < 4; mt++)
#pragma unroll
                    for (int nt = 0; nt < 4; nt++)
                        MMA16816(acc_s[mt][nt], a[mt], b[nt]);
            }

        if (jb == ib) {
#pragma unroll
            for (int mt = 0; mt < 4; mt++) {
                const int r0 = wm + mt * 16 + g;
#pragma unroll
                for (int nt = 0; nt < 4; nt++) {
                    const int c0 = wn + nt * 8 + 2 * t;
                    if (c0     > r0    ) acc_s[mt][nt][0] = -1e30f;
                    if (c0 + 1 > r0    ) acc_s[mt][nt][1] = -1e30f;
                    if (c0     > r0 + 8) acc_s[mt][nt][2] = -1e30f;
                    if (c0 + 1 > r0 + 8) acc_s[mt][nt][3] = -1e30f;
                }
            }
        }

#pragma unroll
        for (int mt = 0; mt < 4; mt++)
#pragma unroll
            for (int h = 0; h < 2; h++) {
                float pm = -1e30f;
#pragma unroll
                for (int nt = 0; nt < 4; nt++)
                    pm = fmaxf(pm, fmaxf(acc_s[mt][nt][2 * h], acc_s[mt][nt][2 * h + 1]));
                pm = fmaxf(pm, __shfl_xor_sync(0xffffffffu, pm, 1));
                pm = fmaxf(pm, __shfl_xor_sync(0xffffffffu, pm, 2));
                if (t == 0) sredm[wm + mt * 16 + g + h * 8][nw] = pm;
            }
        __syncthreads();

        float mnew[8];
#pragma unroll
        for (int mt = 0; mt < 4; mt++)
#pragma unroll
            for (int h = 0; h < 2; h++) {
                const int r = wm + mt * 16 + g + h * 8;
                const float mb = fmaxf(fmaxf(sredm[r][0], sredm[r][1]),
                                       fmaxf(sredm[r][2], sredm[r][3]));
                mnew[mt * 2 + h] = fmaxf(m_i[mt * 2 + h], mb);
            }

#pragma unroll
        for (int mt = 0; mt < 4; mt++)
#pragma unroll
            for (int h = 0; h < 2; h++) {
                const int r = wm + mt * 16 + g + h * 8;
                const float mn = mnew[mt * 2 + h];
                float ps = 0.f;
#pragma unroll
                for (int nt = 0; nt < 4; nt++) {
                    const float e0 = __expf((acc_s[mt][nt][2 * h]     - mn) * scale);
                    const float e1 = __expf((acc_s[mt][nt][2 * h + 1] - mn) * scale);
                    ps += e0 + e1;
                    *(__half2*)(smem + FSM_P + r * 272 + (wn + nt * 8 + 2 * t) * 2) =
                        __floats2half2_rn(e0, e1);
                }
                ps += __shfl_xor_sync(0xffffffffu, ps, 1);
                ps += __shfl_xor_sync(0xffffffffu, ps, 2);
                if (t == 0) sreds[r][nw] = ps;
            }
        __syncthreads();

#pragma unroll
        for (int mt = 0; mt < 4; mt++)
#pragma unroll
            for (int h = 0; h < 2; h++) {
                const int idx = mt * 2 + h;
                const int r = wm + mt * 16 + g + h * 8;
                const float mn = mnew[idx];
                const float alpha = __expf((m_i[idx] - mn) * scale);
                const float bs = sreds[r][0] + sreds[r][1] + sreds[r][2] + sreds[r][3];
                l_i[idx] = alpha * l_i[idx] + bs;
                m_i[idx] = mn;
#pragma unroll
                for (int nt = 0; nt < 4; nt++) {
                    acc_o[mt][nt][2 * h]     *= alpha;
                    acc_o[mt][nt][2 * h + 1] *= alpha;
                }
            }

        const uint32_t pb = smb + FSM_P;
        const uint32_t vb = smb + FSM_V + s * 32768;
#pragma unroll
        for (int kk = 0; kk < 8; kk++) {
            uint32_t a[4][4];
#pragma unroll
            for (int mt = 0; mt < 4; mt++)
                LDSM4(a[mt][0], a[mt][1], a[mt][2], a[mt][3],
                      pb + (uint32_t)(wm + mt * 16 + rA) * 272 + (kk * 2 + ksel) * 16);
            const uint32_t coln = (uint32_t)((((kk & 3) * 2 + ksel) ^ (rA & 7)) << 4);
            uint32_t b[4][2];
#pragma unroll
            for (int pr = 0; pr < 2; pr++) {
                uint32_t r0, r1, r2, r3;
                LDSM4(r0, r1, r2, r3,
                      vb + (kk >> 2) * 16384 + (uint32_t)(wn + pr * 16 + rA) * 128 + coln);
                b[pr * 2][0] = r0; b[pr * 2 + 1][0] = r1;
                b[pr * 2][1] = r2; b[pr * 2 + 1][1] = r3;
            }
#pragma unroll
            for (int mt = 0; mt < 4; mt++)
#pragma unroll
                for (int nt = 0; nt < 4; nt++)
                    MMA16816(acc_o[mt][nt], a[mt], b[nt]);
        }
    }

    __half* gO = g_outh + (size_t)zb * TQ * CH + (size_t)(ib * 128) * CH + zh * HDIM;
#pragma unroll
    for (int mt = 0; mt < 4; mt++)
#pragma unroll
        for (int h = 0; h < 2; h++) {
            const int idx = mt * 2 + h;
            const int r = wm + mt * 16 + g + h * 8;
            const float inv = 1.f / l_i[idx];
#pragma unroll
            for (int nt = 0; nt < 4; nt++) {
                const int c = wn + nt * 8 + 2 * t;
                *(__half2*)(gO + (size_t)r * CH + c) =
                    __floats2half2_rn(acc_o[mt][nt][2 * h] * inv,
                                      acc_o[mt][nt][2 * h + 1] * inv);
            }
        }
}

// ---------------------------------------------------------------------------
__global__ void f2h(const float* __restrict__ s, __half* __restrict__ d, int n4)
{
    int i = blockIdx.x * blockDim.x + threadIdx.x;
    if (i < n4) {
        float4 v = ((const float4*)s)[i];
        ((__half2*)d)[2 * i]     = __floats2half2_rn(v.x, v.y);
        ((__half2*)d)[2 * i + 1] = __floats2half2_rn(v.z, v.w);
    }
}

// ---------------------------------------------------------------------------
__global__ void transV()
{
    __shared__ __half s[32][33];
    const int z = blockIdx.z, b = z >> 4, h = z & 15;
    const __half* src = g_qkvh + (size_t)b * TQ * C3 + 2 * CH + h * HDIM;
    __half* dst = g_vth + (size_t)z * HDIM * TQ;
    const int t0 = blockIdx.x * 32, d0 = blockIdx.y * 32;
    const int tx = threadIdx.x, ty = threadIdx.y;
#pragma unroll
    for (int i = 0; i < 32; i += 8)
        s[ty + i][tx] = src[(size_t)(t0 + ty + i) * C3 + d0 + tx];
    __syncthreads();
#pragma unroll
    for (int i = 0; i < 32; i += 8)
        dst[(size_t)(d0 + ty + i) * TQ + t0 + tx] = s[tx][ty + i];
}

// ---------------------------------------------------------------------------
extern "C" void kernel_launch(void* const* d_in, const int* in_sizes, int n_in,
                              void* d_out, int out_size)
{
    (void)in_sizes; (void)n_in; (void)out_size;
    const float* x  = (const float*)d_in[0];
    const float* Wa = (const float*)d_in[1];
    const float* Wp = (const float*)d_in[2];
    float*       y  = (float*)d_out;

    __half *xh, *wah, *wph, *qkvh, *outh;
    cudaGetSymbolAddress((void**)&xh,   g_xh);
    cudaGetSymbolAddress((void**)&wah,  g_wah);
    cudaGetSymbolAddress((void**)&wph,  g_wph);
    cudaGetSymbolAddress((void**)&qkvh, g_qkvh);
    cudaGetSymbolAddress((void**)&outh, g_outh);

    cudaFuncSetAttribute(gemm_h<true >, cudaFuncAttributeMaxDynamicSharedMemorySize, SMEM_BYTES);
    cudaFuncSetAttribute(gemm_h<false>, cudaFuncAttributeMaxDynamicSharedMemorySize, SMEM_BYTES);
    cudaFuncSetAttribute(flash_attn,    cudaFuncAttributeMaxDynamicSharedMemorySize, FSM_TOTAL);

    // 0) fp32 -> f16 input conversion
    f2h<<<16384, 256>>>(x,  xh,  (BATCH * TQ * CH) / 4);
    f2h<<<12288, 256>>>(Wa, wah, (C3 * CH) / 4);
    f2h<<< 4096, 256>>>(Wp, wph, (CH * CH) / 4);

    // 1) qkv = x @ W_attn^T        M=8192 N=6144 K=2048  (f16 out)
    gemm_h<true><<<dim3(48, 32, 1), 256, SMEM_BYTES>>>(
        xh, CH, wah, CH, qkvh, C3, CH);

    // 1b) V^T per (b,h)
    transV<<<dim3(64, 4, 64), dim3(32, 8)>>>();

    // 2) fused causal attention (QK^T + softmax + PV), O in f16
    flash_attn<<<dim3(16, BATCH * NHEAD), 256, FSM_TOTAL>>>();

    // 3) y = out @ W_proj^T        M=8192 N=2048 K=2048  (f32 out)
    gemm_h<false><<<dim3(16, 32, 1), 256, SMEM_BYTES>>>(
        outh, CH, wph, CH, y, CH, CH);
}